// round 7
// baseline (speedup 1.0000x reference)
#include <cuda_runtime.h>
#include <cuda_bf16.h>

#define NBLK 128
#define NTHR 256
#define BB   128
#define TT   512
#define PREDN 24
#define FF   16
#define LL   8
#define HH   1024
#define FROWS (TT + PREDN - 1)

typedef unsigned int uint;

// ---------------- persistent device scratch ---------------------------------
// A planes (hidden states) in MMA A-fragment order:
//   uint4 index = (rg*64 + kg)*32 + lane, rg = b>>4, kg = u>>4
//   within uint4: halves[ireg*2 + (u&1)], ireg = (r>=8) + 2*(u%16>=8),
//   lane = (b&7... see store_h/load_h for exact mapping.
__device__ uint4 g_A0[2][2][8 * 64 * 32];   // [buf][plane hi/lo][idx]  (1 MB)
__device__ uint4 g_A1[2][2][8 * 64 * 32];
// B (weights) pre-split + pre-permuted into per-thread fragment order:
// [mat][block][nw][hc][plane][lane], uint4 = {b0(kgl0), b1(kgl0), b0(kgl1), b1(kgl1)}
__device__ uint4 g_B[4][NBLK][3][32][2][32];  // 50.3 MB
__device__ float g_p[BB * LL];
__device__ unsigned g_count = 0;
__device__ unsigned g_gen = 0;

// ---------------- grid barrier ----------------------------------------------
__device__ __forceinline__ void gbar() {
    __syncthreads();
    if (threadIdx.x == 0) {
        __threadfence();
        volatile unsigned* vg = &g_gen;
        unsigned g = *vg;
        if (atomicAdd(&g_count, 1u) == NBLK - 1) {
            g_count = 0;
            __threadfence();
            *vg = g + 1;
        } else {
            while (*vg == g) {}
        }
        __threadfence();
    }
    __syncthreads();
}

// ---------------- 2B coherent global ld/st ----------------------------------
__device__ __forceinline__ unsigned short ldcg_u16(const void* p) {
    unsigned short v;
    asm volatile("ld.global.cg.u16 %0, [%1];" : "=h"(v) : "l"(p));
    return v;
}
__device__ __forceinline__ void stcg_u16(void* p, unsigned short v) {
    asm volatile("st.global.cg.u16 [%0], %1;" :: "l"(p), "h"(v));
}

// ---------------- h element <-> fragment-layout mapping ----------------------
__device__ __forceinline__ long h_off(int b, int u) {
    int rg = b >> 4, r = b & 15, kp = u & 15, kg = u >> 4;
    int ireg = (r >> 3) + ((kp >> 3) << 1);
    int ln = (r & 7) * 4 + ((kp & 7) >> 1);
    return ((long)((rg * 64 + kg) * 32 + ln)) * 16 + ireg * 4 + (kp & 1) * 2;
}
__device__ __forceinline__ void store_h(uint4* Ph, uint4* Pl, int b, int u, float v) {
    __nv_bfloat16 hi = __float2bfloat16(v);
    __nv_bfloat16 lo = __float2bfloat16(v - __bfloat162float(hi));
    long off = h_off(b, u);
    stcg_u16((char*)Ph + off, __bfloat16_as_ushort(hi));
    stcg_u16((char*)Pl + off, __bfloat16_as_ushort(lo));
}
__device__ __forceinline__ float load_h(const uint4* Ph, const uint4* Pl, int b, int u) {
    long off = h_off(b, u);
    float hi = __bfloat162float(__ushort_as_bfloat16(ldcg_u16((const char*)Ph + off)));
    float lo = __bfloat162float(__ushort_as_bfloat16(ldcg_u16((const char*)Pl + off)));
    return hi + lo;
}

// ---------------- HMMA m16n8k16 bf16 -> f32 ----------------------------------
__device__ __forceinline__ void mma16816(float* c, const uint* a, uint b0, uint b1) {
    asm volatile(
        "mma.sync.aligned.m16n8k16.row.col.f32.bf16.bf16.f32 "
        "{%0,%1,%2,%3}, {%4,%5,%6,%7}, {%8,%9}, {%0,%1,%2,%3};"
        : "+f"(c[0]), "+f"(c[1]), "+f"(c[2]), "+f"(c[3])
        : "r"(a[0]), "r"(a[1]), "r"(a[2]), "r"(a[3]), "r"(b0), "r"(b1));
}

struct FragHC {
    uint4 ah[2], al[2];   // A hi/lo, [kgl]
    uint4 bh[3], bl[3];   // B hi/lo, [nf]
};

__device__ __forceinline__ void ld_hc(FragHC& f, const uint4* __restrict__ Ah,
                                      const uint4* __restrict__ Al,
                                      const uint4* __restrict__ B0,
                                      int w, int lane, int hc) {
    #pragma unroll
    for (int kgl = 0; kgl < 2; kgl++) {
        int ai = (w * 64 + hc * 2 + kgl) * 32 + lane;
        f.ah[kgl] = __ldcg(Ah + ai);
        f.al[kgl] = __ldcg(Al + ai);
    }
    #pragma unroll
    for (int nf = 0; nf < 3; nf++) {
        const uint4* bp = B0 + nf * 2048 + hc * 64 + lane;
        f.bh[nf] = __ldg(bp);
        f.bl[nf] = __ldg(bp + 32);
    }
}

__device__ __forceinline__ void do_hc(const FragHC& f, float acc[3][4]) {
    #pragma unroll
    for (int kgl = 0; kgl < 2; kgl++) {
        const uint* ah = (const uint*)&f.ah[kgl];
        const uint* al = (const uint*)&f.al[kgl];
        #pragma unroll
        for (int nf = 0; nf < 3; nf++) {
            uint bh0 = kgl ? f.bh[nf].z : f.bh[nf].x;
            uint bh1 = kgl ? f.bh[nf].w : f.bh[nf].y;
            uint bl0 = kgl ? f.bl[nf].z : f.bl[nf].x;
            uint bl1 = kgl ? f.bl[nf].w : f.bl[nf].y;
            mma16816(acc[nf], ah, bh0, bh1);   // hi*hi
            mma16816(acc[nf], al, bh0, bh1);   // lo*hi
            mma16816(acc[nf], ah, bl0, bl1);   // hi*lo
        }
    }
}

// One full K=1024 GEMM slab: warp w owns batch rows [16w,16w+16), all 24 cols.
__device__ void gemm_mma(const uint4* __restrict__ Ah, const uint4* __restrict__ Al,
                         const uint4* __restrict__ B0, int w, int lane,
                         float acc[3][4]) {
    #pragma unroll
    for (int nf = 0; nf < 3; nf++)
        #pragma unroll
        for (int i = 0; i < 4; i++) acc[nf][i] = 0.f;
    FragHC f0, f1;
    ld_hc(f0, Ah, Al, B0, w, lane, 0);
    ld_hc(f1, Ah, Al, B0, w, lane, 1);
    #pragma unroll 1
    for (int hc = 0; hc < 32; hc += 2) {
        do_hc(f0, acc);
        if (hc + 2 < 32) ld_hc(f0, Ah, Al, B0, w, lane, hc + 2);
        do_hc(f1, acc);
        if (hc + 3 < 32) ld_hc(f1, Ah, Al, B0, w, lane, hc + 3);
    }
}

// C fragment -> smem buffer [24 cols][128 b]
__device__ __forceinline__ void epi(const float acc[3][4], float* __restrict__ buf,
                                    int w, int lane) {
    int row = lane >> 2, c2 = (lane & 3) * 2;
    int b = w * 16 + row;
    #pragma unroll
    for (int nf = 0; nf < 3; nf++) {
        int col = nf * 8 + c2;
        buf[col * 128 + b]           = acc[nf][0];
        buf[(col + 1) * 128 + b]     = acc[nf][1];
        buf[col * 128 + b + 8]       = acc[nf][2];
        buf[(col + 1) * 128 + b + 8] = acc[nf][3];
    }
}

// ---------------- small input projection (K = 24) ---------------------------
__device__ __forceinline__ void load_wi_slice(const float* __restrict__ Wih, int u0,
                                              float* __restrict__ sh_wi) {
    for (int idx = threadIdx.x; idx < 24 * 24; idx += NTHR) {
        int jl = idx / 24, k = idx % 24;
        int g = jl >> 3, uu = jl & 7;
        sh_wi[k * 24 + jl] = Wih[(long)(g * HH + u0 + uu) * 24 + k];
    }
}

__device__ __forceinline__ void input_acc24(const float* __restrict__ sh_x,
                                            const float* __restrict__ sh_wi,
                                            int tu, int b0, float ai[3][4]) {
    #pragma unroll
    for (int g = 0; g < 3; g++)
        #pragma unroll
        for (int i = 0; i < 4; i++) ai[g][i] = 0.f;
    #pragma unroll
    for (int k = 0; k < 24; k++) {
        float w0 = sh_wi[k * 24 + tu];
        float w1 = sh_wi[k * 24 + 8 + tu];
        float w2 = sh_wi[k * 24 + 16 + tu];
        #pragma unroll
        for (int i = 0; i < 4; i++) {
            float xv = sh_x[(b0 + i) * 25 + k];
            ai[0][i] += xv * w0; ai[1][i] += xv * w1; ai[2][i] += xv * w2;
        }
    }
}

// ---------------- GRU pointwise update --------------------------------------
__device__ __forceinline__ void gru_upd(const float ai[3][4], const float* __restrict__ s_gh,
                                        const float* __restrict__ bih,
                                        const float* __restrict__ bhh,
                                        int tu, int b0, int jcol,
                                        const uint4* Phc, const uint4* Plc,
                                        uint4* Phn, uint4* Pln) {
    float bir = bih[jcol], biz = bih[HH + jcol], bin = bih[2 * HH + jcol];
    float bhr = bhh[jcol], bhz = bhh[HH + jcol], bhn = bhh[2 * HH + jcol];
    #pragma unroll
    for (int i = 0; i < 4; i++) {
        int b = b0 + i;
        float ahr = s_gh[tu * 128 + b];
        float ahz = s_gh[(8 + tu) * 128 + b];
        float ahn = s_gh[(16 + tu) * 128 + b];
        float r = 1.f / (1.f + __expf(-(ai[0][i] + bir + ahr + bhr)));
        float z = 1.f / (1.f + __expf(-(ai[1][i] + biz + ahz + bhz)));
        float n = tanhf(ai[2][i] + bin + r * (ahn + bhn));
        float ho = load_h(Phc, Plc, b, jcol);
        store_h(Phn, Pln, b, jcol, (1.f - z) * n + z * ho);
    }
}

// ---------------- FC head ----------------------------------------------------
__device__ __forceinline__ void fc_phase(const uint4* Ph, const uint4* Pl,
                                         const float* __restrict__ fcW,
                                         const float* __restrict__ fcb,
                                         float* __restrict__ outp) {
    int b = blockIdx.x;
    int w = threadIdx.x >> 5;
    int lane = threadIdx.x & 31;
    float s = 0.f;
    #pragma unroll
    for (int c = 0; c < 32; c++) {
        int u = c * 32 + lane;
        s += load_h(Ph, Pl, b, u) * fcW[(long)w * HH + u];
    }
    #pragma unroll
    for (int o = 16; o; o >>= 1) s += __shfl_down_sync(0xffffffffu, s, o);
    if (lane == 0) {
        float v = s + fcb[w];
        outp[b * LL + w] = v;
        asm volatile("st.global.cg.f32 [%0], %1;" :: "l"(g_p + b * LL + w), "f"(v));
    }
}

// ---------------- persistent kernel -----------------------------------------
__global__ void __launch_bounds__(NTHR, 1) gru_persistent(
    const float* __restrict__ feats, const float* __restrict__ labels,
    const float* __restrict__ y, const int* __restrict__ teacher,
    const float* __restrict__ eWih0, const float* __restrict__ eWhh0,
    const float* __restrict__ ebih0, const float* __restrict__ ebhh0,
    const float* __restrict__ eWih1, const float* __restrict__ eWhh1,
    const float* __restrict__ ebih1, const float* __restrict__ ebhh1,
    const float* __restrict__ dWih, const float* __restrict__ dWhh,
    const float* __restrict__ dbih, const float* __restrict__ dbhh,
    const float* __restrict__ fcW, const float* __restrict__ fcb,
    float* __restrict__ out)
{
    __shared__ float sh_x[BB * 25];
    __shared__ float sh_wi[24 * 24];
    __shared__ float s_gi[24 * 128];
    __shared__ float s_gh[24 * 128];

    const int t = threadIdx.x;
    const int w = t >> 5;
    const int lane = t & 31;
    const int tu = t & 7;
    const int tb = t >> 3;
    const int b0 = tb * 4;
    const int u0 = blockIdx.x * 8;
    const int jcol = u0 + tu;
    const int teach = teacher[0];

    // ---- zero h (buf 0, both planes) ----
    {
        uint4 z = make_uint4(0, 0, 0, 0);
        int gid = blockIdx.x * NTHR + t;              // NBLK*NTHR == 32768 exactly
        ((uint4*)g_A0)[gid] = z;
        ((uint4*)g_A1)[gid] = z;
    }

    // ---- split + permute weights into fragment order (per block slice) ----
    {
        const float* Wm[4] = {eWhh0, eWih1, eWhh1, dWhh};
        for (int wdx = t; wdx < 4 * 3 * 32 * 2 * 32; wdx += NTHR) {
            int ln = wdx & 31;
            int pl = (wdx >> 5) & 1;
            int hc = (wdx >> 6) & 31;
            int rest = wdx >> 11;
            int nw = rest % 3, m = rest / 3;
            const float* W = Wm[m];
            int u = ln >> 2;
            long wr = (long)(nw * HH + u0 + u) * HH;
            uint vals[4];
            #pragma unroll
            for (int c = 0; c < 4; c++) {
                int k0 = hc * 32 + (c >> 1) * 16 + (c & 1) * 8 + (ln & 3) * 2;
                float2 xv = *reinterpret_cast<const float2*>(W + wr + k0);
                __nv_bfloat16 h0 = __float2bfloat16(xv.x);
                __nv_bfloat16 h1 = __float2bfloat16(xv.y);
                if (pl) {
                    h0 = __float2bfloat16(xv.x - __bfloat162float(h0));
                    h1 = __float2bfloat16(xv.y - __bfloat162float(h1));
                }
                vals[c] = (uint)__bfloat16_as_ushort(h0) |
                          ((uint)__bfloat16_as_ushort(h1) << 16);
            }
            g_B[m][blockIdx.x][nw][hc][pl][ln] = make_uint4(vals[0], vals[1], vals[2], vals[3]);
        }
    }
    load_wi_slice(eWih0, u0, sh_wi);
    gbar();

    int cur = 0;
    float acc[3][4];

    // ================= encoder ==============================================
    for (int step = 0; step < TT; step++) {
        for (int idx = t; idx < BB * 24; idx += NTHR) {
            int b = idx / 24, k = idx % 24;
            float v = (k < FF) ? feats[((long)b * FROWS + step) * FF + k]
                               : labels[((long)b * TT + step) * LL + (k - FF)];
            sh_x[b * 25 + k] = v;
        }
        __syncthreads();

        // layer 0
        gemm_mma(g_A0[cur][0], g_A0[cur][1], &g_B[0][blockIdx.x][0][0][0][0], w, lane, acc);
        epi(acc, s_gh, w, lane);
        __syncthreads();
        {
            float ai[3][4];
            input_acc24(sh_x, sh_wi, tu, b0, ai);
            gru_upd(ai, s_gh, ebih0, ebhh0, tu, b0, jcol,
                    g_A0[cur][0], g_A0[cur][1], g_A0[cur ^ 1][0], g_A0[cur ^ 1][1]);
        }
        gbar();

        // layer 1: gi = Wih1 @ h0_new, gh = Whh1 @ h1_cur
        gemm_mma(g_A0[cur ^ 1][0], g_A0[cur ^ 1][1], &g_B[1][blockIdx.x][0][0][0][0], w, lane, acc);
        epi(acc, s_gi, w, lane);
        gemm_mma(g_A1[cur][0], g_A1[cur][1], &g_B[2][blockIdx.x][0][0][0][0], w, lane, acc);
        epi(acc, s_gh, w, lane);
        __syncthreads();
        {
            float gi[3][4];
            #pragma unroll
            for (int g = 0; g < 3; g++)
                #pragma unroll
                for (int i = 0; i < 4; i++) gi[g][i] = s_gi[(g * 8 + tu) * 128 + b0 + i];
            gru_upd(gi, s_gh, ebih1, ebhh1, tu, b0, jcol,
                    g_A1[cur][0], g_A1[cur][1], g_A1[cur ^ 1][0], g_A1[cur ^ 1][1]);
        }
        gbar();
        cur ^= 1;
    }

    // ps -> out[0] + seed g_p
    fc_phase(g_A1[cur][0], g_A1[cur][1], fcW, fcb, out);
    load_wi_slice(dWih, u0, sh_wi);
    gbar();

    // ================= decoder ==============================================
    for (int s = 0; s < PREDN - 1; s++) {
        for (int idx = t; idx < BB * 24; idx += NTHR) {
            int b = idx / 24, k = idx % 24;
            float v;
            if (k < FF)      v = feats[((long)b * FROWS + TT + s) * FF + k];
            else if (teach)  v = y[((long)b * (PREDN - 1) + s) * LL + (k - FF)];
            else             v = __ldcg(g_p + b * LL + (k - FF));
            sh_x[b * 25 + k] = v;
        }
        __syncthreads();

        gemm_mma(g_A1[cur][0], g_A1[cur][1], &g_B[3][blockIdx.x][0][0][0][0], w, lane, acc);
        epi(acc, s_gh, w, lane);
        __syncthreads();
        {
            float ai[3][4];
            input_acc24(sh_x, sh_wi, tu, b0, ai);
            gru_upd(ai, s_gh, dbih, dbhh, tu, b0, jcol,
                    g_A1[cur][0], g_A1[cur][1], g_A1[cur ^ 1][0], g_A1[cur ^ 1][1]);
        }
        gbar();

        fc_phase(g_A1[cur ^ 1][0], g_A1[cur ^ 1][1], fcW, fcb, out + (long)(s + 1) * BB * LL);
        gbar();
        cur ^= 1;
    }
}

extern "C" void kernel_launch(void* const* d_in, const int* in_sizes, int n_in,
                              void* d_out, int out_size) {
    const float* feats  = (const float*)d_in[0];
    const float* labels = (const float*)d_in[1];
    const float* y      = (const float*)d_in[2];
    const int*   teach  = (const int*)d_in[3];
    const float* eWih0  = (const float*)d_in[4];
    const float* eWhh0  = (const float*)d_in[5];
    const float* ebih0  = (const float*)d_in[6];
    const float* ebhh0  = (const float*)d_in[7];
    const float* eWih1  = (const float*)d_in[8];
    const float* eWhh1  = (const float*)d_in[9];
    const float* ebih1  = (const float*)d_in[10];
    const float* ebhh1  = (const float*)d_in[11];
    const float* dWih   = (const float*)d_in[12];
    const float* dWhh   = (const float*)d_in[13];
    const float* dbih   = (const float*)d_in[14];
    const float* dbhh   = (const float*)d_in[15];
    const float* fcW    = (const float*)d_in[16];
    const float* fcb    = (const float*)d_in[17];
    float* out = (float*)d_out;

    gru_persistent<<<NBLK, NTHR>>>(feats, labels, y, teach,
                                   eWih0, eWhh0, ebih0, ebhh0,
                                   eWih1, eWhh1, ebih1, ebhh1,
                                   dWih, dWhh, dbih, dbhh,
                                   fcW, fcb, out);
}

// round 8
// speedup vs baseline: 1.0396x; 1.0396x over previous
#include <cuda_runtime.h>
#include <cuda_bf16.h>

#define NBLK 128
#define NTHR 256
#define BB   128
#define TT   512
#define PREDN 24
#define FF   16
#define LL   8
#define HH   1024
#define FROWS (TT + PREDN - 1)

typedef unsigned int uint;

// ---------------- persistent device scratch ---------------------------------
// A planes (hidden states) in MMA A-fragment order (same layout as R6).
__device__ uint4 g_A0[2][2][8 * 64 * 32];   // [buf][plane hi/lo]
__device__ uint4 g_A1[2][2][8 * 64 * 32];
// B (weights) split+permuted: [mat][block][nf][hc][pl][ln]
__device__ uint4 g_B[4][NBLK][3][32][2][32];
__device__ float g_p[BB * LL];
__device__ unsigned g_count = 0;
__device__ unsigned g_gen = 0;

// ---------------- grid barrier ----------------------------------------------
__device__ __forceinline__ void gbar() {
    __syncthreads();
    if (threadIdx.x == 0) {
        __threadfence();
        volatile unsigned* vg = &g_gen;
        unsigned g = *vg;
        if (atomicAdd(&g_count, 1u) == NBLK - 1) {
            g_count = 0;
            __threadfence();
            *vg = g + 1;
        } else {
            while (*vg == g) {}
        }
        __threadfence();
    }
    __syncthreads();
}

// ---------------- 2B coherent global ld/st ----------------------------------
__device__ __forceinline__ unsigned short ldcg_u16(const void* p) {
    unsigned short v;
    asm volatile("ld.global.cg.u16 %0, [%1];" : "=h"(v) : "l"(p));
    return v;
}
__device__ __forceinline__ void stcg_u16(void* p, unsigned short v) {
    asm volatile("st.global.cg.u16 [%0], %1;" :: "l"(p), "h"(v));
}

// ---------------- h element <-> fragment-layout mapping ----------------------
__device__ __forceinline__ int h_off(int b, int u) {
    int rg = b >> 4, r = b & 15, kp = u & 15, kg = u >> 4;
    int ireg = (r >> 3) + ((kp >> 3) << 1);
    int ln = (r & 7) * 4 + ((kp & 7) >> 1);
    return ((rg * 64 + kg) * 32 + ln) * 16 + ireg * 4 + (kp & 1) * 2;
}
__device__ __forceinline__ void store_h(uint4* Ph, uint4* Pl, int b, int u, float v) {
    __nv_bfloat16 hi = __float2bfloat16(v);
    __nv_bfloat16 lo = __float2bfloat16(v - __bfloat162float(hi));
    int off = h_off(b, u);
    stcg_u16((char*)Ph + off, __bfloat16_as_ushort(hi));
    stcg_u16((char*)Pl + off, __bfloat16_as_ushort(lo));
}
__device__ __forceinline__ float load_h(const uint4* Ph, const uint4* Pl, int b, int u) {
    int off = h_off(b, u);
    float hi = __bfloat162float(__ushort_as_bfloat16(ldcg_u16((const char*)Ph + off)));
    float lo = __bfloat162float(__ushort_as_bfloat16(ldcg_u16((const char*)Pl + off)));
    return hi + lo;
}

// ---------------- HMMA m16n8k16 bf16 -> f32 ----------------------------------
__device__ __forceinline__ void mma16816(float* c, const uint* a, uint b0, uint b1) {
    asm volatile(
        "mma.sync.aligned.m16n8k16.row.col.f32.bf16.bf16.f32 "
        "{%0,%1,%2,%3}, {%4,%5,%6,%7}, {%8,%9}, {%0,%1,%2,%3};"
        : "+f"(c[0]), "+f"(c[1]), "+f"(c[2]), "+f"(c[3])
        : "r"(a[0]), "r"(a[1]), "r"(a[2]), "r"(a[3]), "r"(b0), "r"(b1));
}

// ---------------- cp.async B staging ------------------------------------------
// smem buffer layout (uint4 index): ((set*4 + hcg)*6 + nf*2 + pl)*32 + ln,
// 1536 uint4 (24576 B) per buffer, 3 buffers.
template<int NSETS>
__device__ __forceinline__ void issue_b(const uint4* __restrict__ B0,
                                        const uint4* __restrict__ B1,
                                        const int* offs, int hc0, uint dst_base, int t) {
    if (NSETS == 2 || t < 128) {
        const uint4* base = ((t < 128) ? B0 : B1) + hc0 * 64;
        uint d = dst_base + t * 96;
        #pragma unroll
        for (int j = 0; j < 6; j++)
            asm volatile("cp.async.cg.shared.global [%0], [%1], 16;"
                         :: "r"(d + j * 16), "l"(base + offs[j]) : "memory");
    }
}

// ---------------- GEMM engine -------------------------------------------------
// 8 warps: warp w owns batch rows [16w,16w+16), all 24 cols, K=1024.
// A: 4-hc register pipeline (ldcg from L2). B: smem triple-buffer via cp.async.
// NSETS=2: set0 (threads 0-127 stage B0) -> accA; set1 (threads 128-255, B1) -> accB.
template<int NSETS>
__device__ void gemm_run(const uint4* __restrict__ Ah, const uint4* __restrict__ Al,
                         const uint4* __restrict__ B0, const uint4* __restrict__ B1,
                         const int* offs, uint4* __restrict__ sB, uint sb_addr,
                         int w, int lane, int t,
                         float accA[3][4], float accB[3][4]) {
    #pragma unroll
    for (int nf = 0; nf < 3; nf++)
        #pragma unroll
        for (int i = 0; i < 4; i++) {
            accA[nf][i] = 0.f;
            if (NSETS == 2) accB[nf][i] = 0.f;
        }

    const uint4* Abh = Ah + w * 2048 + lane;
    const uint4* Abl = Al + w * 2048 + lane;

    __syncthreads();          // previous consumer of sB done
    issue_b<NSETS>(B0, B1, offs, 0, sb_addr, t);
    asm volatile("cp.async.commit_group;" ::: "memory");
    issue_b<NSETS>(B0, B1, offs, 4, sb_addr + 24576, t);
    asm volatile("cp.async.commit_group;" ::: "memory");

    uint4 fah[4][2], fal[4][2];
    #pragma unroll
    for (int j = 0; j < 4; j++) {
        fah[j][0] = __ldcg(Abh + j * 64);   fah[j][1] = __ldcg(Abh + j * 64 + 32);
        fal[j][0] = __ldcg(Abl + j * 64);   fal[j][1] = __ldcg(Abl + j * 64 + 32);
    }

    #pragma unroll 1
    for (int g = 0; g < 8; g++) {
        asm volatile("cp.async.wait_group 1;" ::: "memory");
        __syncthreads();
        if (g + 2 < 8)
            issue_b<NSETS>(B0, B1, offs, (g + 2) * 4, sb_addr + ((g + 2) % 3) * 24576, t);
        asm volatile("cp.async.commit_group;" ::: "memory");
        const uint4* sbuf = sB + (g % 3) * 1536;
        #pragma unroll
        for (int j = 0; j < 4; j++) {
            #pragma unroll
            for (int s = 0; s < NSETS; s++) {
                float (*acc)[4] = s ? accB : accA;
                #pragma unroll
                for (int nf = 0; nf < 3; nf++) {
                    uint4 BH = sbuf[((s * 4 + j) * 6 + nf * 2) * 32 + lane];
                    uint4 BL = sbuf[((s * 4 + j) * 6 + nf * 2 + 1) * 32 + lane];
                    const uint* a0h = (const uint*)&fah[j][0];
                    const uint* a0l = (const uint*)&fal[j][0];
                    const uint* a1h = (const uint*)&fah[j][1];
                    const uint* a1l = (const uint*)&fal[j][1];
                    mma16816(acc[nf], a0h, BH.x, BH.y);
                    mma16816(acc[nf], a0l, BH.x, BH.y);
                    mma16816(acc[nf], a0h, BL.x, BL.y);
                    mma16816(acc[nf], a1h, BH.z, BH.w);
                    mma16816(acc[nf], a1l, BH.z, BH.w);
                    mma16816(acc[nf], a1h, BL.z, BL.w);
                }
            }
            int nhc = 4 * g + 4 + j;
            if (nhc < 32) {
                fah[j][0] = __ldcg(Abh + nhc * 64);  fah[j][1] = __ldcg(Abh + nhc * 64 + 32);
                fal[j][0] = __ldcg(Abl + nhc * 64);  fal[j][1] = __ldcg(Abl + nhc * 64 + 32);
            }
        }
    }
}

// ---------------- in-register GRU update (per MMA lane) ----------------------
__device__ __forceinline__ float sigf(float x) { return 1.f / (1.f + __expf(-x)); }

__device__ __forceinline__ void upd_lane(const float gi[3][4], const float gh[3][4],
                                         const float* __restrict__ bih,
                                         const float* __restrict__ bhh,
                                         int u0, int w, int lane,
                                         const uint4* Phc, const uint4* Plc,
                                         uint4* Phn, uint4* Pln) {
    int r0 = w * 16 + (lane >> 2);
    int c2 = (lane & 3) * 2;
    float bi[2][3], bh[2][3];
    #pragma unroll
    for (int q = 0; q < 2; q++) {
        int jc = u0 + c2 + q;
        bi[q][0] = __ldg(bih + jc);
        bi[q][1] = __ldg(bih + HH + jc);
        bi[q][2] = __ldg(bih + 2 * HH + jc);
        bh[q][0] = __ldg(bhh + jc);
        bh[q][1] = __ldg(bhh + HH + jc);
        bh[q][2] = __ldg(bhh + 2 * HH + jc);
    }
    #pragma unroll
    for (int i = 0; i < 4; i++) {
        int b = r0 + (i >> 1) * 8;
        int q = i & 1;
        int jc = u0 + c2 + q;
        float r = sigf(gi[0][i] + bi[q][0] + gh[0][i] + bh[q][0]);
        float z = sigf(gi[1][i] + bi[q][1] + gh[1][i] + bh[q][1]);
        float n = tanhf(gi[2][i] + bi[q][2] + r * (gh[2][i] + bh[q][2]));
        float ho = Phc ? load_h(Phc, Plc, b, jc) : 0.f;
        store_h(Phn, Pln, b, jc, (1.f - z) * n + z * ho);
    }
}

// input projection (K=24) computed at MMA lane positions
__device__ __forceinline__ void xproj_lane(const float* __restrict__ sh_x,
                                           const float* __restrict__ sh_wi,
                                           int w, int lane, float ai[3][4]) {
    int r0 = w * 16 + (lane >> 2);
    int c2 = (lane & 3) * 2;
    #pragma unroll
    for (int i = 0; i < 4; i++) {
        int b = r0 + (i >> 1) * 8;
        int u = c2 + (i & 1);
        float a0 = 0.f, a1 = 0.f, a2 = 0.f;
        #pragma unroll
        for (int k = 0; k < 24; k++) {
            float xv = sh_x[b * 25 + k];
            a0 += xv * sh_wi[k * 24 + u];
            a1 += xv * sh_wi[k * 24 + 8 + u];
            a2 += xv * sh_wi[k * 24 + 16 + u];
        }
        ai[0][i] = a0; ai[1][i] = a1; ai[2][i] = a2;
    }
}

// ---------------- misc helpers ------------------------------------------------
__device__ __forceinline__ void load_wi_slice(const float* __restrict__ Wih, int u0,
                                              float* __restrict__ sh_wi) {
    for (int idx = threadIdx.x; idx < 24 * 24; idx += NTHR) {
        int jl = idx / 24, k = idx % 24;
        int g = jl >> 3, uu = jl & 7;
        sh_wi[k * 24 + jl] = Wih[(long)(g * HH + u0 + uu) * 24 + k];
    }
}

__device__ __forceinline__ void fc_phase(const uint4* Ph, const uint4* Pl,
                                         const float* __restrict__ fcW,
                                         const float* __restrict__ fcb,
                                         float* __restrict__ outp) {
    int b = blockIdx.x;
    int w = threadIdx.x >> 5;
    int lane = threadIdx.x & 31;
    float s = 0.f;
    #pragma unroll
    for (int c = 0; c < 32; c++) {
        int u = c * 32 + lane;
        s += load_h(Ph, Pl, b, u) * fcW[(long)w * HH + u];
    }
    #pragma unroll
    for (int o = 16; o; o >>= 1) s += __shfl_down_sync(0xffffffffu, s, o);
    if (lane == 0) {
        float v = s + fcb[w];
        outp[b * LL + w] = v;
        asm volatile("st.global.cg.f32 [%0], %1;" :: "l"(g_p + b * LL + w), "f"(v));
    }
}

// ---------------- persistent kernel -----------------------------------------
__global__ void __launch_bounds__(NTHR, 1) gru_persistent(
    const float* __restrict__ feats, const float* __restrict__ labels,
    const float* __restrict__ y, const int* __restrict__ teacher,
    const float* __restrict__ eWih0, const float* __restrict__ eWhh0,
    const float* __restrict__ ebih0, const float* __restrict__ ebhh0,
    const float* __restrict__ eWih1, const float* __restrict__ eWhh1,
    const float* __restrict__ ebih1, const float* __restrict__ ebhh1,
    const float* __restrict__ dWih, const float* __restrict__ dWhh,
    const float* __restrict__ dbih, const float* __restrict__ dbhh,
    const float* __restrict__ fcW, const float* __restrict__ fcb,
    float* __restrict__ out)
{
    extern __shared__ __align__(16) unsigned char smem_raw[];
    uint4* sB    = (uint4*)smem_raw;                      // 3 x 24576 B = 73728 B
    float* sh_x  = (float*)(smem_raw + 73728);            // 12800 B
    float* sh_wi = (float*)(smem_raw + 73728 + 12800);    // 2304 B

    const int t = threadIdx.x;
    const int w = t >> 5;
    const int lane = t & 31;
    const int u0 = blockIdx.x * 8;
    const int teach = teacher[0];
    const uint sb_addr = (uint)__cvta_generic_to_shared(sB);

    // per-thread cp.async source offsets (uint4 units, within matrix slice)
    int offs[6];
    #pragma unroll
    for (int j = 0; j < 6; j++) {
        int li = t * 6 + j;
        int ln = li & 31;
        int q = li >> 5;
        int sub = q % 6;
        int hcg = (q / 6) & 3;
        int nf = sub >> 1, pl = sub & 1;
        offs[j] = nf * 2048 + hcg * 64 + pl * 32 + ln;
    }

    const uint4* Bb0 = &g_B[0][blockIdx.x][0][0][0][0];   // eWhh0
    const uint4* Bb1 = &g_B[1][blockIdx.x][0][0][0][0];   // eWih1
    const uint4* Bb2 = &g_B[2][blockIdx.x][0][0][0][0];   // eWhh1
    const uint4* Bb3 = &g_B[3][blockIdx.x][0][0][0][0];   // dWhh

    // ---- zero h1 buffer 0 (h1(-1) = 0), both planes ----
    {
        uint4 z = make_uint4(0, 0, 0, 0);
        int gid = blockIdx.x * NTHR + t;     // 32768 == uint4 count of g_A1[0]
        ((uint4*)g_A1)[gid] = z;
    }

    // ---- split + permute weights into fragment order (per-block slice) ----
    {
        const float* Wm[4] = {eWhh0, eWih1, eWhh1, dWhh};
        for (int wdx = t; wdx < 4 * 3 * 32 * 2 * 32; wdx += NTHR) {
            int ln = wdx & 31;
            int pl = (wdx >> 5) & 1;
            int hc = (wdx >> 6) & 31;
            int rest = wdx >> 11;
            int nw = rest % 3, m = rest / 3;
            const float* W = Wm[m];
            int u = ln >> 2;
            long wr = (long)(nw * HH + u0 + u) * HH;
            uint vals[4];
            #pragma unroll
            for (int c = 0; c < 4; c++) {
                int k0 = hc * 32 + (c >> 1) * 16 + (c & 1) * 8 + (ln & 3) * 2;
                float2 xv = *reinterpret_cast<const float2*>(W + wr + k0);
                __nv_bfloat16 h0 = __float2bfloat16(xv.x);
                __nv_bfloat16 h1 = __float2bfloat16(xv.y);
                if (pl) {
                    h0 = __float2bfloat16(xv.x - __bfloat162float(h0));
                    h1 = __float2bfloat16(xv.y - __bfloat162float(h1));
                }
                vals[c] = (uint)__bfloat16_as_ushort(h0) |
                          ((uint)__bfloat16_as_ushort(h1) << 16);
            }
            g_B[m][blockIdx.x][nw][hc][pl][ln] = make_uint4(vals[0], vals[1], vals[2], vals[3]);
        }
    }
    load_wi_slice(eWih0, u0, sh_wi);

    // ---- prologue: h0(0) = GRU(x(0), h=0) -> g_A0[0] ----
    for (int idx = t; idx < BB * 24; idx += NTHR) {
        int b = idx / 24, k = idx % 24;
        float v = (k < FF) ? feats[((long)b * FROWS) * FF + k]
                           : labels[((long)b * TT) * LL + (k - FF)];
        sh_x[b * 25 + k] = v;
    }
    __syncthreads();
    {
        float ai[3][4], zg[3][4];
        #pragma unroll
        for (int g = 0; g < 3; g++)
            #pragma unroll
            for (int i = 0; i < 4; i++) zg[g][i] = 0.f;
        xproj_lane(sh_x, sh_wi, w, lane, ai);
        upd_lane(ai, zg, ebih0, ebhh0, u0, w, lane,
                 nullptr, nullptr, g_A0[0][0], g_A0[0][1]);
    }
    gbar();

    float accA[3][4], accB[3][4], accC[3][4];

    // ================= encoder: merged phases (1 gbar/step) ==================
    for (int step = 0; step < TT; step++) {
        int rb = step & 1, wb = rb ^ 1;

        if (step + 1 < TT) {
            for (int idx = t; idx < BB * 24; idx += NTHR) {
                int b = idx / 24, k = idx % 24;
                float v = (k < FF) ? feats[((long)b * FROWS + step + 1) * FF + k]
                                   : labels[((long)b * TT + step + 1) * LL + (k - FF)];
                sh_x[b * 25 + k] = v;
            }
        }

        // dual GEMM on A = h0(step): accA = Wih1 gates, accB = Whh0 gates (t+1)
        gemm_run<2>(g_A0[rb][0], g_A0[rb][1], Bb1, Bb0, offs, sB, sb_addr,
                    w, lane, t, accA, accB);
        // single GEMM on A = h1(step-1): accC = Whh1 gates
        gemm_run<1>(g_A1[rb][0], g_A1[rb][1], Bb2, Bb2, offs, sB, sb_addr,
                    w, lane, t, accC, accC);

        // h1(step) = GRU(gi=accA, gh=accC, h1_old)
        upd_lane(accA, accC, ebih1, ebhh1, u0, w, lane,
                 g_A1[rb][0], g_A1[rb][1], g_A1[wb][0], g_A1[wb][1]);
        // h0(step+1) = GRU(xproj(step+1), gh=accB, h0_old)
        if (step + 1 < TT) {
            float ai[3][4];
            xproj_lane(sh_x, sh_wi, w, lane, ai);
            upd_lane(ai, accB, ebih0, ebhh0, u0, w, lane,
                     g_A0[rb][0], g_A0[rb][1], g_A0[wb][0], g_A0[wb][1]);
        }
        gbar();
    }

    // ps -> out[0] + seed g_p  (final h1 in buffer 0: last write wb = 0)
    fc_phase(g_A1[0][0], g_A1[0][1], fcW, fcb, out);
    load_wi_slice(dWih, u0, sh_wi);
    gbar();

    // ================= decoder ==============================================
    for (int s = 0; s < PREDN - 1; s++) {
        int rb = s & 1, wb = rb ^ 1;
        for (int idx = t; idx < BB * 24; idx += NTHR) {
            int b = idx / 24, k = idx % 24;
            float v;
            if (k < FF)      v = feats[((long)b * FROWS + TT + s) * FF + k];
            else if (teach)  v = y[((long)b * (PREDN - 1) + s) * LL + (k - FF)];
            else             v = __ldcg(g_p + b * LL + (k - FF));
            sh_x[b * 25 + k] = v;
        }

        gemm_run<1>(g_A1[rb][0], g_A1[rb][1], Bb3, Bb3, offs, sB, sb_addr,
                    w, lane, t, accC, accC);
        {
            float ai[3][4];
            xproj_lane(sh_x, sh_wi, w, lane, ai);
            upd_lane(ai, accC, dbih, dbhh, u0, w, lane,
                     g_A1[rb][0], g_A1[rb][1], g_A1[wb][0], g_A1[wb][1]);
        }
        gbar();

        fc_phase(g_A1[wb][0], g_A1[wb][1], fcW, fcb, out + (long)(s + 1) * BB * LL);
        gbar();
    }
}

extern "C" void kernel_launch(void* const* d_in, const int* in_sizes, int n_in,
                              void* d_out, int out_size) {
    const float* feats  = (const float*)d_in[0];
    const float* labels = (const float*)d_in[1];
    const float* y      = (const float*)d_in[2];
    const int*   teach  = (const int*)d_in[3];
    const float* eWih0  = (const float*)d_in[4];
    const float* eWhh0  = (const float*)d_in[5];
    const float* ebih0  = (const float*)d_in[6];
    const float* ebhh0  = (const float*)d_in[7];
    const float* eWih1  = (const float*)d_in[8];
    const float* eWhh1  = (const float*)d_in[9];
    const float* ebih1  = (const float*)d_in[10];
    const float* ebhh1  = (const float*)d_in[11];
    const float* dWih   = (const float*)d_in[12];
    const float* dWhh   = (const float*)d_in[13];
    const float* dbih   = (const float*)d_in[14];
    const float* dbhh   = (const float*)d_in[15];
    const float* fcW    = (const float*)d_in[16];
    const float* fcb    = (const float*)d_in[17];
    float* out = (float*)d_out;

    static int smem_set = 0;
    if (!smem_set) {
        cudaFuncSetAttribute(gru_persistent,
                             cudaFuncAttributeMaxDynamicSharedMemorySize, 88832);
        smem_set = 1;
    }

    gru_persistent<<<NBLK, NTHR, 88832>>>(feats, labels, y, teach,
                                          eWih0, eWhh0, ebih0, ebhh0,
                                          eWih1, eWhh1, ebih1, ebhh1,
                                          dWih, dWhh, dbih, dbhh,
                                          fcW, fcb, out);
}